// round 9
// baseline (speedup 1.0000x reference)
#include <cuda_runtime.h>
#include <cstddef>

#define TT 64
#define LL 512
#define BB 512
#define START_TAG 62
#define STOP_TAG  63
#define NBLK (BB / 2)          // 2 sequences per block

// Scratch (allocation-free requirement).
__device__ float g_partials[BB];
__device__ int   g_count;      // zero-init; reset by last block each launch

#define HBAR(id) asm volatile("bar.sync %0, 64;" :: "r"(id) : "memory")

__device__ __forceinline__ void fma2(unsigned long long& acc,
                                     unsigned long long p,
                                     unsigned long long q) {
    asm("fma.rn.f32x2 %0, %1, %2, %0;" : "+l"(acc) : "l"(p), "l"(q));
}
__device__ __forceinline__ void add2(unsigned long long& a, unsigned long long b) {
    asm("add.rn.f32x2 %0, %0, %1;" : "+l"(a) : "l"(b));
}
__device__ __forceinline__ float2 unpack2(unsigned long long v) {
    float2 r;
    asm("mov.b64 {%0, %1}, %2;" : "=f"(r.x), "=f"(r.y) : "l"(v));
    return r;
}
__device__ __forceinline__ unsigned long long pack2(float lo, float hi) {
    unsigned long long v;
    asm("mov.b64 %0, {%1, %2};" : "=l"(v) : "f"(lo), "f"(hi));
    return v;
}

// Full 64-dot (R4-proven body). Broadcast LDS.128: all lanes read same address.
__device__ __forceinline__ float dot64(const float* __restrict__ qbuf,
                                       const unsigned long long* __restrict__ P2) {
    const ulonglong2* q4 = (const ulonglong2*)qbuf;
    unsigned long long a0 = 0, a1 = 0, a2 = 0, a3 = 0;
#pragma unroll
    for (int k = 0; k < TT / 8; ++k) {
        ulonglong2 v = q4[2 * k];
        ulonglong2 w = q4[2 * k + 1];
        fma2(a0, P2[4 * k + 0], v.x);
        fma2(a1, P2[4 * k + 1], v.y);
        fma2(a2, P2[4 * k + 2], w.x);
        fma2(a3, P2[4 * k + 3], w.y);
    }
    add2(a0, a1);
    add2(a2, a3);
    add2(a0, a2);
    float2 sp = unpack2(a0);
    return sp.x + sp.y;
}

__global__ void __launch_bounds__(128) crf_fused_kernel(
    const float* __restrict__ inputs,   // (B, L, T)
    const int*   __restrict__ tags,     // (B, L)
    const int*   __restrict__ mask,     // (B, L)
    const float* __restrict__ trans,    // (T, T)
    float*       __restrict__ out)
{
    const int tid  = threadIdx.x;
    const int wid  = tid >> 5;
    const int lane = tid & 31;
    // SMSP-spread grouping: group g owns warps {g, g+2} -> SMSPs {g, g+2}.
    const int g   = wid & 1;
    const int l   = ((wid >> 1) << 5) + lane;   // tag 0..63 within group
    const int bar = 1 + g;
    const int seq = blockIdx.x * 2 + g;

    __shared__ __align__(16) float q_sh[2][2][TT];  // [group][buf][tag]
    __shared__ float red2[2][TT];
    __shared__ float dsl[2];
    __shared__ int   flagW[4];
    __shared__ int   islast;

    // Packed exp(transition) row for destination tag = l.
    unsigned long long P2[TT / 2];
#pragma unroll
    for (int j = 0; j < TT / 2; ++j) {
        float p0 = __expf(trans[l * TT + 2 * j]);
        float p1 = __expf(trans[l * TT + 2 * j + 1]);
        P2[j] = pack2(p0, p1);
    }

    // all-ones mask detection for this group's sequence.
    int m_and = 1;
    for (int t = l; t < LL; t += 64)
        m_and &= (mask[seq * LL + t] != 0);
    flagW[wid] = __all_sync(0xffffffffu, m_and);
    HBAR(bar);
    const int all_ones = flagW[g] & flagW[2 + g];

    const float* ep = inputs + (size_t)seq * LL * TT + l;

    float a, C;

    if (all_ones) {
        // ===== fast path: prob-space recursion (R4-proven numerics) ==========
        q_sh[g][0][l] = (l == START_TAG) ? 1.0f : 0.0f;

        float e0 = ep[0 * TT], e1 = ep[1 * TT], e2 = ep[2 * TT], e3 = ep[3 * TT];
        int Dint = 0;
        HBAR(bar);

#pragma unroll 4
        for (int t = 0; t < LL; ++t) {
            float e_pf = (t + 4 < LL) ? ep[(t + 4) * TT] : 0.0f;
            const float E = __expf(e0);

            const int bu = t & 1;
            const float* qb = q_sh[g][bu];

            // Power-of-two renorm from q[0] exponent field (ALU-only, off-chain).
            const float q0 = qb[0];
            const unsigned ebits = __float_as_uint(q0) & 0x7f800000u;
            const float r = ebits ? __uint_as_float(0x7f000000u - ebits) : 1.0f;
            Dint += ebits ? ((int)(ebits >> 23) - 127) : 0;
            const float mult = E * r;

            const float s = dot64(qb, P2);          // the only on-chain work
            q_sh[g][bu ^ 1][l] = s * mult;
            HBAR(bar);

            e0 = e1; e1 = e2; e2 = e3; e3 = e_pf;
        }

        const float qf = q_sh[g][0][l];
        a = (qf > 0.0f) ? __logf(qf) : -1.0e30f;
        C = (float)Dint * 0.6931471805599453f;
    } else {
        // ===== general masked path (log space; rare, correctness-first) ======
        a = (l == START_TAG) ? 0.0f : -10000.0f;
        C = 0.0f;
        for (int t = 0; t < LL; ++t) {
            q_sh[g][0][l] = __expf(a);
            HBAR(bar);
            const float mf = (float)mask[seq * LL + t];
            float s;
            if (mf != 0.0f) {
                s = dot64(q_sh[g][0], P2);
            } else {
                float acc = 0.f;
#pragma unroll
                for (int j = 0; j < TT; ++j) acc += q_sh[g][0][j];
                s = acc;
            }
            float d = fmaf(mf, ep[t * TT], __logf(s));
            d = fmaxf(d, -1.0e30f);
            if (l == 0) dsl[g] = d;
            HBAR(bar);
            const float d0 = dsl[g];
            a = d - d0;
            C += d0;
        }
    }

    // ================= per-sequence finale (group-local reductions) ==========
    const float term = fmaxf(a + trans[STOP_TAG * TT + l], -1.0e30f);
    red2[g][l] = term;
    HBAR(bar);
#pragma unroll
    for (int off = TT / 2; off > 0; off >>= 1) {
        if (l < off) red2[g][l] = fmaxf(red2[g][l], red2[g][l + off]);
        HBAR(bar);
    }
    const float mx = red2[g][0];
    HBAR(bar);
    red2[g][l] = __expf(term - mx);
    HBAR(bar);
#pragma unroll
    for (int off = TT / 2; off > 0; off >>= 1) {
        if (l < off) red2[g][l] += red2[g][l + off];
        HBAR(bar);
    }
    const float logden = C + mx + __logf(red2[g][0]);
    HBAR(bar);

    // numerator path score (gold tags)
    float sc = 0.f;
    const float* in_b = inputs + (size_t)seq * LL * TT;
    const int*   tg   = tags + seq * LL;
    const int*   mk   = mask + seq * LL;
    for (int t = l; t < LL - 1; t += 64) {
        const int pt = tg[t];
        const int nt = tg[t + 1];
        sc += trans[nt * TT + pt] * (float)mk[t + 1]
            + in_b[t * TT + pt] * (float)mk[t];
    }
    red2[g][l] = sc;
    HBAR(bar);
#pragma unroll
    for (int off = TT / 2; off > 0; off >>= 1) {
        if (l < off) red2[g][l] += red2[g][l + off];
        HBAR(bar);
    }
    if (l == 0) {
        const int t0  = tg[0];
        const int tl_ = tg[LL - 1];
        float score = red2[g][0]
                    + trans[t0 * TT + START_TAG]
                    + trans[STOP_TAG * TT + tl_]
                    + in_b[(LL - 1) * TT + tl_] * (float)mk[LL - 1];
        g_partials[seq] = score - logden;
    }

    // ---- deterministic fixed-order final reduction in the last block ----
    __syncthreads();
    if (tid == 0) {
        __threadfence();
        int old = atomicAdd(&g_count, 1);
        islast = (old == (int)gridDim.x - 1);
    }
    __syncthreads();
    if (islast) {
        __threadfence();
        float s = 0.f;
#pragma unroll
        for (int k = 0; k < 4; ++k)            // 128 threads x 4 = 512, fixed order
            s += g_partials[tid * 4 + k];
        float* rf = &red2[0][0];               // 128 contiguous floats
        rf[tid] = s;
        __syncthreads();
#pragma unroll
        for (int off = 64; off > 0; off >>= 1) {
            if (tid < off) rf[tid] += rf[tid + off];
            __syncthreads();
        }
        if (tid == 0) {
            out[0] = rf[0];
            g_count = 0;
        }
    }
}

extern "C" void kernel_launch(void* const* d_in, const int* in_sizes, int n_in,
                              void* d_out, int out_size)
{
    const float* inputs = (const float*)d_in[0];
    const int*   tags   = (const int*)d_in[1];
    const int*   mask   = (const int*)d_in[2];
    const float* trans  = (const float*)d_in[3];

    crf_fused_kernel<<<NBLK, 128>>>(inputs, tags, mask, trans, (float*)d_out);
}

// round 10
// speedup vs baseline: 1.3396x; 1.3396x over previous
#include <cuda_runtime.h>
#include <cstddef>

#define TT 64
#define LL 512
#define BB 512
#define START_TAG 62
#define STOP_TAG  63
#define NBLK (BB / 2)          // 2 sequences per block

// Scratch (allocation-free requirement).
__device__ float g_partials[BB];
__device__ int   g_count;      // zero-init; reset by last block each launch

#define HBAR(id) asm volatile("bar.sync %0, 64;" :: "r"(id) : "memory")

__device__ __forceinline__ void fma2(unsigned long long& acc,
                                     unsigned long long p,
                                     unsigned long long q) {
    asm("fma.rn.f32x2 %0, %1, %2, %0;" : "+l"(acc) : "l"(p), "l"(q));
}
__device__ __forceinline__ void add2(unsigned long long& a, unsigned long long b) {
    asm("add.rn.f32x2 %0, %0, %1;" : "+l"(a) : "l"(b));
}
__device__ __forceinline__ float2 unpack2(unsigned long long v) {
    float2 r;
    asm("mov.b64 {%0, %1}, %2;" : "=f"(r.x), "=f"(r.y) : "l"(v));
    return r;
}
__device__ __forceinline__ unsigned long long pack2(float lo, float hi) {
    unsigned long long v;
    asm("mov.b64 %0, {%1, %2};" : "=l"(v) : "f"(lo), "f"(hi));
    return v;
}

// Full 64-dot (R4-proven body). Broadcast LDS.128: all lanes read same address.
__device__ __forceinline__ float dot64(const float* __restrict__ qbuf,
                                       const unsigned long long* __restrict__ P2) {
    const ulonglong2* q4 = (const ulonglong2*)qbuf;
    unsigned long long a0 = 0, a1 = 0, a2 = 0, a3 = 0;
#pragma unroll
    for (int k = 0; k < TT / 8; ++k) {
        ulonglong2 v = q4[2 * k];
        ulonglong2 w = q4[2 * k + 1];
        fma2(a0, P2[4 * k + 0], v.x);
        fma2(a1, P2[4 * k + 1], v.y);
        fma2(a2, P2[4 * k + 2], w.x);
        fma2(a3, P2[4 * k + 3], w.y);
    }
    add2(a0, a1);
    add2(a2, a3);
    add2(a0, a2);
    float2 sp = unpack2(a0);
    return sp.x + sp.y;
}

// __launch_bounds__(128, 1): min-blocks=1 lifts the ptxas occupancy heuristic's
// 96-reg cap (which spilled the 64-register P2 array to local in R9).
__global__ void __launch_bounds__(128, 1) crf_fused_kernel(
    const float* __restrict__ inputs,   // (B, L, T)
    const int*   __restrict__ tags,     // (B, L)
    const int*   __restrict__ mask,     // (B, L)
    const float* __restrict__ trans,    // (T, T)
    float*       __restrict__ out)
{
    const int tid  = threadIdx.x;
    const int wid  = tid >> 5;
    const int lane = tid & 31;
    // SMSP-spread grouping: group g owns warps {g, g+2} -> SMSPs {g, g+2}.
    const int g   = wid & 1;
    const int l   = ((wid >> 1) << 5) + lane;   // tag 0..63 within group
    const int bar = 1 + g;
    const int seq = blockIdx.x * 2 + g;

    __shared__ __align__(16) float q_sh[2][2][TT];  // [group][buf][tag]
    __shared__ float red2[2][TT];
    __shared__ float dsl[2];
    __shared__ int   flagW[4];
    __shared__ int   islast;

    // Packed exp(transition) row for destination tag = l.
    unsigned long long P2[TT / 2];
#pragma unroll
    for (int j = 0; j < TT / 2; ++j) {
        float p0 = __expf(trans[l * TT + 2 * j]);
        float p1 = __expf(trans[l * TT + 2 * j + 1]);
        P2[j] = pack2(p0, p1);
    }

    // all-ones mask detection for this group's sequence.
    int m_and = 1;
    for (int t = l; t < LL; t += 64)
        m_and &= (mask[seq * LL + t] != 0);
    flagW[wid] = __all_sync(0xffffffffu, m_and);
    HBAR(bar);
    const int all_ones = flagW[g] & flagW[2 + g];

    const float* ep = inputs + (size_t)seq * LL * TT + l;

    float a, C;

    if (all_ones) {
        // ===== fast path: prob-space recursion (R4-proven numerics) ==========
        q_sh[g][0][l] = (l == START_TAG) ? 1.0f : 0.0f;

        float e0 = ep[0 * TT], e1 = ep[1 * TT], e2 = ep[2 * TT], e3 = ep[3 * TT];
        int Dint = 0;
        HBAR(bar);

#pragma unroll 4
        for (int t = 0; t < LL; ++t) {
            float e_pf = (t + 4 < LL) ? ep[(t + 4) * TT] : 0.0f;
            const float E = __expf(e0);

            const int bu = t & 1;
            const float* qb = q_sh[g][bu];

            // Power-of-two renorm from q[0] exponent field (ALU-only, off-chain).
            const float q0 = qb[0];
            const unsigned ebits = __float_as_uint(q0) & 0x7f800000u;
            const float r = ebits ? __uint_as_float(0x7f000000u - ebits) : 1.0f;
            Dint += ebits ? ((int)(ebits >> 23) - 127) : 0;
            const float mult = E * r;

            const float s = dot64(qb, P2);          // the only on-chain work
            q_sh[g][bu ^ 1][l] = s * mult;
            HBAR(bar);

            e0 = e1; e1 = e2; e2 = e3; e3 = e_pf;
        }

        const float qf = q_sh[g][0][l];
        a = (qf > 0.0f) ? __logf(qf) : -1.0e30f;
        C = (float)Dint * 0.6931471805599453f;
    } else {
        // ===== general masked path (log space; rare, correctness-first) ======
        a = (l == START_TAG) ? 0.0f : -10000.0f;
        C = 0.0f;
        for (int t = 0; t < LL; ++t) {
            q_sh[g][0][l] = __expf(a);
            HBAR(bar);
            const float mf = (float)mask[seq * LL + t];
            float s;
            if (mf != 0.0f) {
                s = dot64(q_sh[g][0], P2);
            } else {
                float acc = 0.f;
#pragma unroll
                for (int j = 0; j < TT; ++j) acc += q_sh[g][0][j];
                s = acc;
            }
            float d = fmaf(mf, ep[t * TT], __logf(s));
            d = fmaxf(d, -1.0e30f);
            if (l == 0) dsl[g] = d;
            HBAR(bar);
            const float d0 = dsl[g];
            a = d - d0;
            C += d0;
        }
    }

    // ================= per-sequence finale (group-local reductions) ==========
    const float term = fmaxf(a + trans[STOP_TAG * TT + l], -1.0e30f);
    red2[g][l] = term;
    HBAR(bar);
#pragma unroll
    for (int off = TT / 2; off > 0; off >>= 1) {
        if (l < off) red2[g][l] = fmaxf(red2[g][l], red2[g][l + off]);
        HBAR(bar);
    }
    const float mx = red2[g][0];
    HBAR(bar);
    red2[g][l] = __expf(term - mx);
    HBAR(bar);
#pragma unroll
    for (int off = TT / 2; off > 0; off >>= 1) {
        if (l < off) red2[g][l] += red2[g][l + off];
        HBAR(bar);
    }
    const float logden = C + mx + __logf(red2[g][0]);
    HBAR(bar);

    // numerator path score (gold tags)
    float sc = 0.f;
    const float* in_b = inputs + (size_t)seq * LL * TT;
    const int*   tg   = tags + seq * LL;
    const int*   mk   = mask + seq * LL;
    for (int t = l; t < LL - 1; t += 64) {
        const int pt = tg[t];
        const int nt = tg[t + 1];
        sc += trans[nt * TT + pt] * (float)mk[t + 1]
            + in_b[t * TT + pt] * (float)mk[t];
    }
    red2[g][l] = sc;
    HBAR(bar);
#pragma unroll
    for (int off = TT / 2; off > 0; off >>= 1) {
        if (l < off) red2[g][l] += red2[g][l + off];
        HBAR(bar);
    }
    if (l == 0) {
        const int t0  = tg[0];
        const int tl_ = tg[LL - 1];
        float score = red2[g][0]
                    + trans[t0 * TT + START_TAG]
                    + trans[STOP_TAG * TT + tl_]
                    + in_b[(LL - 1) * TT + tl_] * (float)mk[LL - 1];
        g_partials[seq] = score - logden;
    }

    // ---- deterministic fixed-order final reduction in the last block ----
    __syncthreads();
    if (tid == 0) {
        __threadfence();
        int old = atomicAdd(&g_count, 1);
        islast = (old == (int)gridDim.x - 1);
    }
    __syncthreads();
    if (islast) {
        __threadfence();
        float s = 0.f;
#pragma unroll
        for (int k = 0; k < 4; ++k)            // 128 threads x 4 = 512, fixed order
            s += g_partials[tid * 4 + k];
        float* rf = &red2[0][0];               // 128 contiguous floats
        rf[tid] = s;
        __syncthreads();
#pragma unroll
        for (int off = 64; off > 0; off >>= 1) {
            if (tid < off) rf[tid] += rf[tid + off];
            __syncthreads();
        }
        if (tid == 0) {
            out[0] = rf[0];
            g_count = 0;
        }
    }
}

extern "C" void kernel_launch(void* const* d_in, const int* in_sizes, int n_in,
                              void* d_out, int out_size)
{
    const float* inputs = (const float*)d_in[0];
    const int*   tags   = (const int*)d_in[1];
    const int*   mask   = (const int*)d_in[2];
    const float* trans  = (const float*)d_in[3];

    crf_fused_kernel<<<NBLK, 128>>>(inputs, tags, mask, trans, (float*)d_out);
}

// round 11
// speedup vs baseline: 1.6812x; 1.2550x over previous
#include <cuda_runtime.h>
#include <cstddef>

#define TT 64
#define LL 512
#define BB 512
#define START_TAG 62
#define STOP_TAG  63
#define WPB 4                  // warps (sequences) per block
#define NBLK (BB / WPB)        // 128 blocks

// Scratch (allocation-free requirement).
__device__ float g_partials[BB];
__device__ int   g_count;      // zero-init; reset by last block each launch

#define FULLMASK 0xffffffffu

__device__ __forceinline__ void fma2(unsigned long long& acc,
                                     unsigned long long p,
                                     unsigned long long q) {
    asm("fma.rn.f32x2 %0, %1, %2, %0;" : "+l"(acc) : "l"(p), "l"(q));
}
__device__ __forceinline__ void add2(unsigned long long& a, unsigned long long b) {
    asm("add.rn.f32x2 %0, %0, %1;" : "+l"(a) : "l"(b));
}
__device__ __forceinline__ float2 unpack2(unsigned long long v) {
    float2 r;
    asm("mov.b64 {%0, %1}, %2;" : "=f"(r.x), "=f"(r.y) : "l"(v));
    return r;
}
__device__ __forceinline__ unsigned long long pack2(float lo, float hi) {
    unsigned long long v;
    asm("mov.b64 %0, {%1, %2};" : "=l"(v) : "f"(lo), "f"(hi));
    return v;
}

__device__ __forceinline__ float warp_sum(float v) {
#pragma unroll
    for (int o = 16; o > 0; o >>= 1) v += __shfl_xor_sync(FULLMASK, v, o);
    return v;
}
__device__ __forceinline__ float warp_max(float v) {
#pragma unroll
    for (int o = 16; o > 0; o >>= 1) v = fmaxf(v, __shfl_xor_sync(FULLMASK, v, o));
    return v;
}

// Dual 64-dot for this thread's two output tags (rows in P2a / P2b).
__device__ __forceinline__ void dot64_pair(const float* __restrict__ qbuf,
                                           const unsigned long long* __restrict__ P2a,
                                           const unsigned long long* __restrict__ P2b,
                                           float& s0, float& s1) {
    const ulonglong2* q4 = (const ulonglong2*)qbuf;
    unsigned long long a0 = 0, a1 = 0, b0 = 0, b1 = 0;
#pragma unroll
    for (int k = 0; k < 16; ++k) {
        ulonglong2 v = q4[k];
        fma2(a0, P2a[2 * k],     v.x);
        fma2(a1, P2a[2 * k + 1], v.y);
        fma2(b0, P2b[2 * k],     v.x);
        fma2(b1, P2b[2 * k + 1], v.y);
    }
    add2(a0, a1);
    add2(b0, b1);
    float2 pa = unpack2(a0);
    float2 pb = unpack2(b0);
    s0 = pa.x + pa.y;
    s1 = pb.x + pb.y;
}

__global__ void __launch_bounds__(32 * WPB, 1) crf_fused_kernel(
    const float* __restrict__ inputs,   // (B, L, T)
    const int*   __restrict__ tags,     // (B, L)
    const int*   __restrict__ mask,     // (B, L)
    const float* __restrict__ trans,    // (T, T)
    float*       __restrict__ out)
{
    const int tid  = threadIdx.x;
    const int wid  = tid >> 5;
    const int l    = tid & 31;          // owns tags 2l, 2l+1
    const int i0   = 2 * l;
    const int i1   = 2 * l + 1;
    const int seq  = blockIdx.x * WPB + wid;

    __shared__ __align__(16) float q_sh[WPB][2][TT];  // per-warp double buffer
    __shared__ float rf[32 * WPB];
    __shared__ int   islast;

    // Packed exp(transition) rows for this thread's two destination tags.
    unsigned long long P2a[TT / 2], P2b[TT / 2];
#pragma unroll
    for (int j = 0; j < TT / 2; ++j) {
        P2a[j] = pack2(__expf(trans[i0 * TT + 2 * j]), __expf(trans[i0 * TT + 2 * j + 1]));
        P2b[j] = pack2(__expf(trans[i1 * TT + 2 * j]), __expf(trans[i1 * TT + 2 * j + 1]));
    }

    // all-ones mask detection for this warp's sequence (warp-local).
    int m_and = 1;
    for (int t = l; t < LL; t += 32)
        m_and &= (mask[seq * LL + t] != 0);
    const int all_ones = __all_sync(FULLMASK, m_and);

    // Emissions as float2 (tags 2l, 2l+1 are contiguous): 32 float2 per step.
    const float2* ep2 = (const float2*)(inputs + (size_t)seq * LL * TT) + l;

    float a0, a1, C;

    if (all_ones) {
        // ===== fast path: prob-space recursion, warp-synchronous =============
        ((float2*)q_sh[wid][0])[l] =
            make_float2((i0 == START_TAG) ? 1.0f : 0.0f,
                        (i1 == START_TAG) ? 1.0f : 0.0f);

        float2 e0 = ep2[0 * 32], e1 = ep2[1 * 32], e2 = ep2[2 * 32], e3 = ep2[3 * 32];
        int Dint = 0;
        __syncwarp();

#pragma unroll 4
        for (int t = 0; t < LL; ++t) {
            float2 e_pf = (t + 4 < LL) ? ep2[(t + 4) * 32] : make_float2(0.f, 0.f);

            const float E0 = __expf(e0.x);
            const float E1 = __expf(e0.y);

            const int bu = t & 1;
            const float* qb = q_sh[wid][bu];

            // Power-of-two renorm from q[0]'s exponent field (ALU only).
            const float q0 = qb[0];
            const unsigned ebits = __float_as_uint(q0) & 0x7f800000u;
            const float r = ebits ? __uint_as_float(0x7f000000u - ebits) : 1.0f;
            Dint += ebits ? ((int)(ebits >> 23) - 127) : 0;
            const float m0 = E0 * r;
            const float m1 = E1 * r;

            float s0, s1;
            dot64_pair(qb, P2a, P2b, s0, s1);
            ((float2*)q_sh[wid][bu ^ 1])[l] = make_float2(s0 * m0, s1 * m1);
            __syncwarp();

            e0 = e1; e1 = e2; e2 = e3; e3 = e_pf;
        }

        const float2 qf = ((const float2*)q_sh[wid][0])[l];
        a0 = (qf.x > 0.0f) ? __logf(qf.x) : -1.0e30f;
        a1 = (qf.y > 0.0f) ? __logf(qf.y) : -1.0e30f;
        C  = (float)Dint * 0.6931471805599453f;
    } else {
        // ===== general masked path (log space; rare, correctness-first) ======
        a0 = (i0 == START_TAG) ? 0.0f : -10000.0f;
        a1 = (i1 == START_TAG) ? 0.0f : -10000.0f;
        C  = 0.0f;
        for (int t = 0; t < LL; ++t) {
            const int bu = t & 1;
            ((float2*)q_sh[wid][bu])[l] = make_float2(__expf(a0), __expf(a1));
            __syncwarp();
            const float* qb = q_sh[wid][bu];

            const float mf = (float)mask[seq * LL + t];
            float s0, s1;
            if (mf != 0.0f) {
                dot64_pair(qb, P2a, P2b, s0, s1);
            } else {
                float acc = 0.f;
#pragma unroll
                for (int j = 0; j < TT; ++j) acc += qb[j];
                s0 = s1 = acc;
            }

            const float2 e = ep2[t * 32];
            float d0 = fmaf(mf, e.x, __logf(s0));
            float d1 = fmaf(mf, e.y, __logf(s1));
            d0 = fmaxf(d0, -1.0e30f);
            d1 = fmaxf(d1, -1.0e30f);
            const float anchor = __shfl_sync(FULLMASK, d0, 0);  // d of tag 0
            a0 = d0 - anchor;
            a1 = d1 - anchor;
            C += anchor;
            __syncwarp();
        }
    }

    // ============== per-sequence finale (all warp-local, shuffle-based) ======
    float t0 = fmaxf(a0 + trans[STOP_TAG * TT + i0], -1.0e30f);
    float t1 = fmaxf(a1 + trans[STOP_TAG * TT + i1], -1.0e30f);
    const float mx = warp_max(fmaxf(t0, t1));
    const float sm = warp_sum(__expf(t0 - mx) + __expf(t1 - mx));
    const float logden = C + mx + __logf(sm);

    // numerator path score (gold tags)
    float sc = 0.f;
    const float* in_b = inputs + (size_t)seq * LL * TT;
    const int*   tg   = tags + seq * LL;
    const int*   mk   = mask + seq * LL;
    for (int t = l; t < LL - 1; t += 32) {
        const int pt = tg[t];
        const int nt = tg[t + 1];
        sc += trans[nt * TT + pt] * (float)mk[t + 1]
            + in_b[t * TT + pt] * (float)mk[t];
    }
    sc = warp_sum(sc);
    if (l == 0) {
        const int tfirst = tg[0];
        const int tlast  = tg[LL - 1];
        float score = sc
                    + trans[tfirst * TT + START_TAG]
                    + trans[STOP_TAG * TT + tlast]
                    + in_b[(LL - 1) * TT + tlast] * (float)mk[LL - 1];
        g_partials[seq] = score - logden;
    }

    // ---- deterministic fixed-order final reduction in the last block ----
    __syncthreads();
    if (tid == 0) {
        __threadfence();
        int old = atomicAdd(&g_count, 1);
        islast = (old == (int)gridDim.x - 1);
    }
    __syncthreads();
    if (islast) {
        __threadfence();
        float s = 0.f;
#pragma unroll
        for (int k = 0; k < BB / (32 * WPB); ++k)      // fixed order: 4 adds
            s += g_partials[tid * (BB / (32 * WPB)) + k];
        rf[tid] = s;
        __syncthreads();
#pragma unroll
        for (int off = (32 * WPB) / 2; off > 0; off >>= 1) {
            if (tid < off) rf[tid] += rf[tid + off];
            __syncthreads();
        }
        if (tid == 0) {
            out[0] = rf[0];
            g_count = 0;
        }
    }
}

extern "C" void kernel_launch(void* const* d_in, const int* in_sizes, int n_in,
                              void* d_out, int out_size)
{
    const float* inputs = (const float*)d_in[0];
    const int*   tags   = (const int*)d_in[1];
    const int*   mask   = (const int*)d_in[2];
    const float* trans  = (const float*)d_in[3];

    crf_fused_kernel<<<NBLK, 32 * WPB>>>(inputs, tags, mask, trans, (float*)d_out);
}